// round 7
// baseline (speedup 1.0000x reference)
#include <cuda_runtime.h>
#include <cuda_bf16.h>
#include <cstdint>
#include <math.h>

// Problem constants
#define BATCH 2
#define SEQ   2048
#define DIM   1024
#define HEADS 16
#define DHEAD 64
#define INNER 1024
#define QKV_COLS 3072
#define MROWS 4096              // BATCH*SEQ
#define ATT_SCALE 0.125f
#define LOG2E 1.4426950408889634f

// Scratch (device globals — no cudaMalloc allowed). hi/lo stored as separate
// K=1024 planes; GEMM fuses the 3 split terms in-register.
__device__ __nv_bfloat16 g_xh [(size_t)MROWS * 1024];
__device__ __nv_bfloat16 g_xl [(size_t)MROWS * 1024];
__device__ __nv_bfloat16 g_wqh[(size_t)QKV_COLS * 1024];   // w_qkv^T hi
__device__ __nv_bfloat16 g_wql[(size_t)QKV_COLS * 1024];
__device__ __nv_bfloat16 g_woh[(size_t)DIM * 1024];        // w_out^T hi
__device__ __nv_bfloat16 g_wol[(size_t)DIM * 1024];
__device__ __nv_bfloat16 g_oh [(size_t)MROWS * 1024];      // attn out hi
__device__ __nv_bfloat16 g_ol [(size_t)MROWS * 1024];
__device__ __nv_bfloat16 g_qh [(size_t)MROWS * INNER];     // Q hi [b*n][h*64+d]
__device__ __nv_bfloat16 g_ql [(size_t)MROWS * INNER];
__device__ __nv_bfloat16 g_kh [(size_t)MROWS * INNER];
__device__ __nv_bfloat16 g_kl [(size_t)MROWS * INNER];
__device__ __nv_bfloat16 g_vth[(size_t)32 * 64 * SEQ];     // V^T hi [bh][d][n]
__device__ __nv_bfloat16 g_vtl[(size_t)32 * 64 * SEQ];
__device__ float g_vst[(size_t)MROWS * INNER];             // V fp32 staging

// ---------------------------------------------------------------------------
// PTX helpers (sm_80-compatible only; harness lowers via virtual compute_103)
// ---------------------------------------------------------------------------
__device__ __forceinline__ uint32_t smem_u32(const void* p) {
    uint32_t a;
    asm("{ .reg .u64 t; cvta.to.shared.u64 t, %1; cvt.u32.u64 %0, t; }"
        : "=r"(a) : "l"(p));
    return a;
}
#define SWZ128(o) ((o) ^ (((o) >> 3) & 0x70))
#define CP16(dst, src)  asm volatile("cp.async.cg.shared.global [%0], [%1], 16;" :: "r"(dst), "l"(src) : "memory")
#define CP_COMMIT()     asm volatile("cp.async.commit_group;" ::: "memory")
#define CP_WAIT1()      asm volatile("cp.async.wait_group 1;" ::: "memory")
#define CP_WAIT0()      asm volatile("cp.async.wait_group 0;" ::: "memory")

#define LDSM4(r0, r1, r2, r3, addr) \
    asm volatile("ldmatrix.sync.aligned.m8n8.x4.shared.b16 {%0,%1,%2,%3}, [%4];" \
                 : "=r"(r0), "=r"(r1), "=r"(r2), "=r"(r3) : "r"(addr))

#define MMA16816(d, a, b0, b1) \
    asm volatile("mma.sync.aligned.m16n8k16.row.col.f32.bf16.bf16.f32 " \
                 "{%0,%1,%2,%3}, {%4,%5,%6,%7}, {%8,%9}, {%0,%1,%2,%3};" \
                 : "+f"((d)[0]), "+f"((d)[1]), "+f"((d)[2]), "+f"((d)[3]) \
                 : "r"((a)[0]), "r"((a)[1]), "r"((a)[2]), "r"((a)[3]), \
                   "r"(b0), "r"(b1))

__device__ __forceinline__ uint32_t packbf(float lo, float hi) {
    uint32_t r;
    asm("cvt.rn.bf16x2.f32 %0, %1, %2;" : "=r"(r) : "f"(hi), "f"(lo));
    return r;
}
__device__ __forceinline__ void split2(float v0, float v1,
                                       uint32_t& hi, uint32_t& lo) {
    hi = packbf(v0, v1);
    float h0 = __uint_as_float(hi << 16);
    float h1 = __uint_as_float(hi & 0xffff0000u);
    lo = packbf(v0 - h0, v1 - h1);
}

// ---------------------------------------------------------------------------
// Input split kernels
// ---------------------------------------------------------------------------
__global__ void split_a_kernel(const float* __restrict__ in,
                               __nv_bfloat16* __restrict__ oh,
                               __nv_bfloat16* __restrict__ ol, int n)
{
    int idx = blockIdx.x * 256 + threadIdx.x;
    if (idx >= n) return;
    float v = in[idx];
    __nv_bfloat16 hi = __float2bfloat16(v);
    oh[idx] = hi;
    ol[idx] = __float2bfloat16(v - __bfloat162float(hi));
}

// Weights [1024 x N] -> transposed hi/lo [N x 1024]
__global__ void split_w_kernel(const float* __restrict__ w,
                               __nv_bfloat16* __restrict__ wh,
                               __nv_bfloat16* __restrict__ wl, int N)
{
    __shared__ float t[32][33];
    int bk = blockIdx.y * 32, bn = blockIdx.x * 32;
    int tx = threadIdx.x, ty = threadIdx.y;   // (32, 8)
#pragma unroll
    for (int i = 0; i < 4; i++)
        t[ty + 8 * i][tx] = w[(size_t)(bk + ty + 8 * i) * N + bn + tx];
    __syncthreads();
#pragma unroll
    for (int i = 0; i < 4; i++) {
        int n = bn + ty + 8 * i, k = bk + tx;
        float v = t[tx][ty + 8 * i];
        __nv_bfloat16 hi = __float2bfloat16(v);
        size_t o = (size_t)n * 1024 + k;
        wh[o] = hi;
        wl[o] = __float2bfloat16(v - __bfloat162float(hi));
    }
}

// V fp32 staging [b*n][h*64+d] -> V^T hi/lo [bh][d][n]
__global__ void split_vt_kernel(const float* __restrict__ vst,
                                __nv_bfloat16* __restrict__ vth,
                                __nv_bfloat16* __restrict__ vtl)
{
    __shared__ float t[32][33];
    int bh = blockIdx.z, b = bh >> 4, h = bh & 15;
    int n0 = blockIdx.x * 32, d0 = blockIdx.y * 32;
    int tx = threadIdx.x, ty = threadIdx.y;   // (32, 8)
#pragma unroll
    for (int i = 0; i < 4; i++)
        t[ty + 8 * i][tx] =
            vst[(size_t)(b * SEQ + n0 + ty + 8 * i) * 1024 + h * 64 + d0 + tx];
    __syncthreads();
#pragma unroll
    for (int i = 0; i < 4; i++) {
        int d = d0 + ty + 8 * i;
        float v = t[tx][ty + 8 * i];
        __nv_bfloat16 hi = __float2bfloat16(v);
        __nv_bfloat16 lo = __float2bfloat16(v - __bfloat162float(hi));
        size_t o = (size_t)(bh * 64 + d) * SEQ + n0 + tx;
        vth[o] = hi; vtl[o] = lo;
    }
}

// ---------------------------------------------------------------------------
// Fused-split bf16 GEMM: C = (Ah+Al)(Bh+Bl)^T ~= AhBh + AlBh + AhBl, fp32 acc.
// K=1024, chunk k=32 (NCHUNK 32), 3-stage cp.async, 128x128 tile, 256 thr.
// Stage (32KB): sA 16KB = 128 rows x [Ah 64B | Al 64B]; sB same for Wh|Wl.
// ---------------------------------------------------------------------------
#define STAGE2 32768
#define GSMEM_BYTES (3 * STAGE2)
#define NCHUNK 32

__device__ __forceinline__ void gemm_load_chunk(
    uint32_t sb, int stage, int chunk, int tid,
    const __nv_bfloat16* __restrict__ Ah, const __nv_bfloat16* __restrict__ Al,
    const __nv_bfloat16* __restrict__ Bh, const __nv_bfloat16* __restrict__ Bl,
    int row0, int col0)
{
    uint32_t sA = sb + stage * STAGE2;
    uint32_t sB = sA + 16384;
    int k0 = chunk * 32;
#pragma unroll
    for (int i = 0; i < 4; i++) {
        int g = tid + i * 256;          // 0..1023
        int row = g >> 3, c16 = g & 7;  // granules 0-3: hi, 4-7: lo
        uint32_t off = SWZ128((uint32_t)(row * 128 + c16 * 16));
        const __nv_bfloat16* a = (c16 < 4) ? Ah : Al;
        const __nv_bfloat16* b = (c16 < 4) ? Bh : Bl;
        int kk = k0 + (c16 & 3) * 8;
        CP16(sA + off, a + (size_t)(row0 + row) * 1024 + kk);
        CP16(sB + off, b + (size_t)(col0 + row) * 1024 + kk);
    }
}

__global__ __launch_bounds__(256, 2)
void mma_gemm_kernel(const __nv_bfloat16* __restrict__ Ah,
                     const __nv_bfloat16* __restrict__ Al,
                     const __nv_bfloat16* __restrict__ Bh,
                     const __nv_bfloat16* __restrict__ Bl,
                     float* __restrict__ C, int N, int mode,
                     __nv_bfloat16* __restrict__ qh, __nv_bfloat16* __restrict__ ql,
                     __nv_bfloat16* __restrict__ kh, __nv_bfloat16* __restrict__ kl,
                     float* __restrict__ vst)
{
    extern __shared__ char smem[];
    uint32_t sb = smem_u32(smem);
    const int tid  = threadIdx.x;
    const int lane = tid & 31;
    const int wid  = tid >> 5;
    const int wm   = wid & 3;
    const int wn   = wid >> 2;
    const int row0 = blockIdx.y * 128;
    const int col0 = blockIdx.x * 128;

    float acc[2][8][4];
#pragma unroll
    for (int mt = 0; mt < 2; mt++)
#pragma unroll
        for (int nt = 0; nt < 8; nt++)
#pragma unroll
            for (int v = 0; v < 4; v++) acc[mt][nt][v] = 0.0f;

    gemm_load_chunk(sb, 0, 0, tid, Ah, Al, Bh, Bl, row0, col0);
    CP_COMMIT();
    gemm_load_chunk(sb, 1, 1, tid, Ah, Al, Bh, Bl, row0, col0);
    CP_COMMIT();

    const int arow_l = wm * 32 + (lane & 15);
    const int brow_l = wn * 64 + (lane & 15);
    const int khalf  = (lane >> 4) * 16;

    for (int c = 0; c < NCHUNK; c++) {
        CP_WAIT1();
        __syncthreads();

        int nc = c + 2;
        if (nc < NCHUNK)
            gemm_load_chunk(sb, nc % 3, nc, tid, Ah, Al, Bh, Bl, row0, col0);
        CP_COMMIT();

        uint32_t sA = sb + (c % 3) * STAGE2;
        uint32_t sB = sA + 16384;

#pragma unroll
        for (int ks = 0; ks < 2; ks++) {
            const uint32_t kb = (uint32_t)(ks * 32 + khalf);
            uint32_t ah[2][4], al2[2][4], bb[4][4];
#pragma unroll
            for (int mt = 0; mt < 2; mt++) {
                uint32_t rb = (uint32_t)((arow_l + mt * 16) * 128);
                LDSM4(ah[mt][0], ah[mt][1], ah[mt][2], ah[mt][3],
                      sA + SWZ128(rb + kb));
                LDSM4(al2[mt][0], al2[mt][1], al2[mt][2], al2[mt][3],
                      sA + SWZ128(rb + 64 + kb));
            }
            // Wh pass: Ah*Wh + Al*Wh
#pragma unroll
            for (int np = 0; np < 4; np++)
                LDSM4(bb[np][0], bb[np][1], bb[np][2], bb[np][3],
                      sB + SWZ128((uint32_t)((brow_l + np * 16) * 128) + kb));
#pragma unroll
            for (int mt = 0; mt < 2; mt++)
#pragma unroll
                for (int nt = 0; nt < 8; nt++) {
                    int np = nt >> 1, sel = nt & 1;
                    MMA16816(acc[mt][nt], ah[mt],  bb[np][sel], bb[np][2 + sel]);
                    MMA16816(acc[mt][nt], al2[mt], bb[np][sel], bb[np][2 + sel]);
                }
            // Wl pass: Ah*Wl
#pragma unroll
            for (int np = 0; np < 4; np++)
                LDSM4(bb[np][0], bb[np][1], bb[np][2], bb[np][3],
                      sB + SWZ128((uint32_t)((brow_l + np * 16) * 128) + 64 + kb));
#pragma unroll
            for (int mt = 0; mt < 2; mt++)
#pragma unroll
                for (int nt = 0; nt < 8; nt++) {
                    int np = nt >> 1, sel = nt & 1;
                    MMA16816(acc[mt][nt], ah[mt], bb[np][sel], bb[np][2 + sel]);
                }
        }
    }

    const int g = lane >> 2, t = lane & 3;
#pragma unroll
    for (int mt = 0; mt < 2; mt++) {
        int r0 = row0 + wm * 32 + mt * 16 + g;
#pragma unroll
        for (int nt = 0; nt < 8; nt++) {
            int col = col0 + wn * 64 + nt * 8 + t * 2;
            if (mode == 0) {
                *(float2*)&C[(size_t)r0 * N + col] =
                    make_float2(acc[mt][nt][0], acc[mt][nt][1]);
                *(float2*)&C[(size_t)(r0 + 8) * N + col] =
                    make_float2(acc[mt][nt][2], acc[mt][nt][3]);
            } else {
                int sec = col >> 10, cc = col & 1023;
                if (sec == 2) {
                    *(float2*)&vst[(size_t)r0 * 1024 + cc] =
                        make_float2(acc[mt][nt][0], acc[mt][nt][1]);
                    *(float2*)&vst[(size_t)(r0 + 8) * 1024 + cc] =
                        make_float2(acc[mt][nt][2], acc[mt][nt][3]);
                } else {
                    __nv_bfloat16* dh = sec ? kh : qh;
                    __nv_bfloat16* dl = sec ? kl : ql;
                    uint32_t hi, lo;
                    split2(acc[mt][nt][0], acc[mt][nt][1], hi, lo);
                    *(uint32_t*)&dh[(size_t)r0 * 1024 + cc] = hi;
                    *(uint32_t*)&dl[(size_t)r0 * 1024 + cc] = lo;
                    split2(acc[mt][nt][2], acc[mt][nt][3], hi, lo);
                    *(uint32_t*)&dh[(size_t)(r0 + 8) * 1024 + cc] = hi;
                    *(uint32_t*)&dl[(size_t)(r0 + 8) * 1024 + cc] = lo;
                }
            }
        }
    }
}

// ---------------------------------------------------------------------------
// Flash attention on mma.sync bf16, register-resident Q and P, j-tile 64,
// smem ~97KB -> 2 CTAs/SM. grid (16 i-tiles, 32 bh), 8 warps (16 rows each).
// SMEM: QH 0, QL 16384; stages s=0,1 at 32768+s*32768:
//       KH+0, KL+8192 (64 j-rows x 64k, 128B rows), VH+16384, VL+24576
//       (64 d-rows x 64 j, 128B rows); MASK 98304 + s*256. Total 98816.
// ---------------------------------------------------------------------------
#define AT_QH   0
#define AT_QL   16384
#define AT_STG  32768
#define AT_KH   0
#define AT_KL   8192
#define AT_VH   16384
#define AT_VL   24576
#define AT_MASK 98304
#define AT_SMEM 98816

__device__ __forceinline__ void attn_load_stage(
    uint32_t sb, int stage, int j0, int tid, int b, int bh,
    const __nv_bfloat16* __restrict__ kh, const __nv_bfloat16* __restrict__ kl,
    const __nv_bfloat16* __restrict__ vth, const __nv_bfloat16* __restrict__ vtl,
    const float* __restrict__ mask)
{
    uint32_t st = sb + AT_STG + stage * 32768;
    const int h = bh & 15;
    const __nv_bfloat16* khg = kh + (size_t)(b * SEQ + j0) * 1024 + h * 64;
    const __nv_bfloat16* klg = kl + (size_t)(b * SEQ + j0) * 1024 + h * 64;
#pragma unroll
    for (int i = 0; i < 2; i++) {
        int t = tid + i * 256;          // 0..511
        int row = t >> 3, c = t & 7;
        uint32_t off = SWZ128((uint32_t)(row * 128 + c * 16));
        CP16(st + AT_KH + off, khg + (size_t)row * 1024 + c * 8);
        CP16(st + AT_KL + off, klg + (size_t)row * 1024 + c * 8);
    }
    const __nv_bfloat16* vhg = vth + (size_t)(bh * 64) * SEQ + j0;
    const __nv_bfloat16* vlg = vtl + (size_t)(bh * 64) * SEQ + j0;
#pragma unroll
    for (int i = 0; i < 2; i++) {
        int t = tid + i * 256;          // 0..511
        int d = t >> 3, c = t & 7;
        uint32_t off = SWZ128((uint32_t)(d * 128 + c * 16));
        CP16(st + AT_VH + off, vhg + (size_t)d * SEQ + c * 8);
        CP16(st + AT_VL + off, vlg + (size_t)d * SEQ + c * 8);
    }
    if (tid < 16)
        CP16(sb + AT_MASK + stage * 256 + tid * 16, mask + b * SEQ + j0 + tid * 4);
}

__global__ __launch_bounds__(256, 2)
void attn_mma_kernel(const __nv_bfloat16* __restrict__ qh,
                     const __nv_bfloat16* __restrict__ ql,
                     const __nv_bfloat16* __restrict__ kh,
                     const __nv_bfloat16* __restrict__ kl,
                     const __nv_bfloat16* __restrict__ vth,
                     const __nv_bfloat16* __restrict__ vtl,
                     const float* __restrict__ mask,
                     __nv_bfloat16* __restrict__ oh,
                     __nv_bfloat16* __restrict__ ol)
{
    extern __shared__ char smem[];
    uint32_t sb = smem_u32(smem);
    const int tid = threadIdx.x, lane = tid & 31, w = tid >> 5;
    const int g = lane >> 2, t4 = lane & 3;
    const int l16 = lane & 15, khalf = (lane >> 4) * 16;
    const int bh = blockIdx.y, b = bh >> 4, h = bh & 15;
    const int i0 = blockIdx.x * 128;

    // async-load Q tile (hi+lo) as its own commit group
    {
        const __nv_bfloat16* qhg = qh + (size_t)(b * SEQ + i0) * 1024 + h * 64;
        const __nv_bfloat16* qlg = ql + (size_t)(b * SEQ + i0) * 1024 + h * 64;
#pragma unroll
        for (int i = 0; i < 4; i++) {
            int t = tid + i * 256;
            int row = t >> 3, c = t & 7;
            uint32_t off = SWZ128((uint32_t)(row * 128 + c * 16));
            CP16(sb + AT_QH + off, qhg + (size_t)row * 1024 + c * 8);
            CP16(sb + AT_QL + off, qlg + (size_t)row * 1024 + c * 8);
        }
    }
    CP_COMMIT();
    attn_load_stage(sb, 0, 0, tid, b, bh, kh, kl, vth, vtl, mask);
    CP_COMMIT();

    // Q fragments -> registers
    CP_WAIT1();
    __syncthreads();
    uint32_t qfh[4][4], qfl[4][4];
    const uint32_t qrow = (uint32_t)((w * 16 + l16) * 128);
#pragma unroll
    for (int ks = 0; ks < 4; ks++) {
        uint32_t kb = (uint32_t)(ks * 32 + khalf);
        LDSM4(qfh[ks][0], qfh[ks][1], qfh[ks][2], qfh[ks][3],
              sb + AT_QH + SWZ128(qrow + kb));
        LDSM4(qfl[ks][0], qfl[ks][1], qfl[ks][2], qfl[ks][3],
              sb + AT_QL + SWZ128(qrow + kb));
    }

    float m0 = -1e30f, m1 = -1e30f, lsum0 = 0.0f, lsum1 = 0.0f;
    float o[8][4];
#pragma unroll
    for (int nt = 0; nt < 8; nt++)
#pragma unroll
        for (int v = 0; v < 4; v++) o[nt][v] = 0.0f;

    const float MSC = ATT_SCALE * LOG2E;   // logits in log2 domain

    for (int jt = 0; jt < 32; jt++) {
        CP_WAIT0();
        __syncthreads();
        if (jt + 1 < 32)
            attn_load_stage(sb, (jt + 1) & 1, (jt + 1) * 64, tid, b, bh,
                            kh, kl, vth, vtl, mask);
        CP_COMMIT();

        uint32_t stg = sb + AT_STG + (jt & 1) * 32768;
        const float* maskS = (const float*)(smem + AT_MASK + (jt & 1) * 256);

        // ---- S = Q K^T : fused (Qh+Ql)*Kh pass + Qh*Kl pass ----
        float s[8][4];
#pragma unroll
        for (int nt = 0; nt < 8; nt++)
#pragma unroll
            for (int v = 0; v < 4; v++) s[nt][v] = 0.0f;

#pragma unroll
        for (int ks = 0; ks < 4; ks++) {
            const uint32_t kb = (uint32_t)(ks * 32 + khalf);
#pragma unroll
            for (int np = 0; np < 4; np++) {
                uint32_t b4[4];
                LDSM4(b4[0], b4[1], b4[2], b4[3],
                      stg + AT_KH + SWZ128((uint32_t)((np * 16 + l16) * 128) + kb));
                MMA16816(s[np * 2],     qfh[ks], b4[0], b4[2]);
                MMA16816(s[np * 2 + 1], qfh[ks], b4[1], b4[3]);
                MMA16816(s[np * 2],     qfl[ks], b4[0], b4[2]);
                MMA16816(s[np * 2 + 1], qfl[ks], b4[1], b4[3]);
            }
        }
#pragma unroll
        for (int ks = 0; ks < 4; ks++) {
            const uint32_t kb = (uint32_t)(ks * 32 + khalf);
#pragma unroll
            for (int np = 0; np < 4; np++) {
                uint32_t b4[4];
                LDSM4(b4[0], b4[1], b4[2], b4[3],
                      stg + AT_KL + SWZ128((uint32_t)((np * 16 + l16) * 128) + kb));
                MMA16816(s[np * 2],     qfh[ks], b4[0], b4[2]);
                MMA16816(s[np * 2 + 1], qfh[ks], b4[1], b4[3]);
            }
        }

        // ---- mask*scale*log2e, online softmax (log2 domain) ----
        float rm0 = -1e30f, rm1 = -1e30f;
#pragma unroll
        for (int nt = 0; nt < 8; nt++) {
            float2 mk = *(const float2*)&maskS[nt * 8 + t4 * 2];
            mk.x *= MSC; mk.y *= MSC;
            s[nt][0] *= mk.x; s[nt][1] *= mk.y;
            s[nt][2] *= mk.x; s[nt][3] *= mk.y;
            rm0 = fmaxf(rm0, fmaxf(s[nt][0], s[nt][1]));
            rm1 = fmaxf(rm1, fmaxf(s[nt][2], s[nt][3]));
        }
        rm0 = fmaxf(rm0, __shfl_xor_sync(0xffffffffu, rm0, 1));
        rm0 = fmaxf(rm0, __shfl_xor_sync(0xffffffffu, rm0, 2));
        rm1 = fmaxf(rm1, __shfl_xor_sync(0xffffffffu, rm1, 1));
        rm1 = fmaxf(rm1, __shfl_xor_sync(0xffffffffu, rm1, 2));
        float mn0 = fmaxf(m0, rm0), mn1 = fmaxf(m1, rm1);
        float al0 = exp2f(m0 - mn0), al1 = exp2f(m1 - mn1);
        m0 = mn0; m1 = mn1;
        lsum0 *= al0; lsum1 *= al1;
#pragma unroll
        for (int nt = 0; nt < 8; nt++) {
            o[nt][0] *= al0; o[nt][1] *= al0;
            o[nt][2] *= al1; o[nt][3] *= al1;
        }
        float ps0 = 0.0f, ps1 = 0.0f;
#pragma unroll
        for (int nt = 0; nt < 8; nt++) {
            s[nt][0] = exp2f(s[nt][0] - m0);
            s[nt][1] = exp2f(s[nt][1] - m0);
            s[nt][2] = exp2f(s[nt][2] - m1);
            s[nt][3] = exp2f(s[nt][3] - m1);
            ps0 += s[nt][0] + s[nt][1];
            ps1 += s[nt][2] + s[nt][3];
        }
        lsum0 += ps0; lsum1 += ps1;

        // ---- pack P fragments (S accum frag == A operand frag layout) ----
        uint32_t ph[4][4], pl[4][4];
#pragma unroll
        for (int ks = 0; ks < 4; ks++) {
            split2(s[2 * ks][0],     s[2 * ks][1],     ph[ks][0], pl[ks][0]);
            split2(s[2 * ks][2],     s[2 * ks][3],     ph[ks][1], pl[ks][1]);
            split2(s[2 * ks + 1][0], s[2 * ks + 1][1], ph[ks][2], pl[ks][2]);
            split2(s[2 * ks + 1][2], s[2 * ks + 1][3], ph[ks][3], pl[ks][3]);
        }

        // ---- O += P V : fused (Ph+Pl)*Vh pass + Ph*Vl pass ----
#pragma unroll
        for (int ks = 0; ks < 4; ks++) {
            const uint32_t kb = (uint32_t)(ks * 32 + khalf);
#pragma unroll
            for (int np = 0; np < 4; np++) {
                uint32_t b4[4];
                LDSM4(b4[0], b4[1], b4[2], b4[3],
                      stg + AT_VH + SWZ128((uint32_t)((np * 16 + l16) * 128) + kb));
                MMA16816(o[np * 2],     ph[ks], b4[0], b4[2]);
                MMA16816(o[np * 2 + 1], ph[ks], b4[1], b4[3]);
                MMA16816(o[np * 2],     pl[ks], b4[0], b4[2]);
                MMA16816(o[np * 2 + 1], pl[ks], b4[1], b4[3]);
            }
        }
#pragma unroll
        for (int ks = 0; ks < 4; ks++) {
            const uint32_t kb = (uint32_t)(ks * 32 + khalf);
#pragma unroll
            for (int np = 0; np < 4; np++) {
                uint32_t b4[4];
                LDSM4(b4[0], b4[1], b4[2], b4[3],
                      stg + AT_VL + SWZ128((uint32_t)((np * 16 + l16) * 128) + kb));
                MMA16816(o[np * 2],     ph[ks], b4[0], b4[2]);
                MMA16816(o[np * 2 + 1], ph[ks], b4[1], b4[3]);
            }
        }
    }

    // ---- finalize: reduce l over quad, normalize, write hi/lo planes ----
    lsum0 += __shfl_xor_sync(0xffffffffu, lsum0, 1);
    lsum0 += __shfl_xor_sync(0xffffffffu, lsum0, 2);
    lsum1 += __shfl_xor_sync(0xffffffffu, lsum1, 1);
    lsum1 += __shfl_xor_sync(0xffffffffu, lsum1, 2);
    float inv0 = 1.0f / lsum0, inv1 = 1.0f / lsum1;

    const int r0 = i0 + w * 16 + g, r1 = r0 + 8;
#pragma unroll
    for (int nt = 0; nt < 8; nt++) {
        int col = nt * 8 + t4 * 2;
        uint32_t hi, lo;
        size_t base0 = (size_t)(b * SEQ + r0) * 1024 + h * 64 + col;
        split2(o[nt][0] * inv0, o[nt][1] * inv0, hi, lo);
        *(uint32_t*)&oh[base0] = hi;
        *(uint32_t*)&ol[base0] = lo;
        size_t base1 = (size_t)(b * SEQ + r1) * 1024 + h * 64 + col;
        split2(o[nt][2] * inv1, o[nt][3] * inv1, hi, lo);
        *(uint32_t*)&oh[base1] = hi;
        *(uint32_t*)&ol[base1] = lo;
    }
}

// ---------------------------------------------------------------------------
// Launch
// ---------------------------------------------------------------------------
extern "C" void kernel_launch(void* const* d_in, const int* in_sizes, int n_in,
                              void* d_out, int out_size)
{
    const float* x     = (const float*)d_in[0];
    const float* smask = (const float*)d_in[1];
    const float* wqkv  = (const float*)d_in[2];
    const float* wout  = (const float*)d_in[3];
    float* out = (float*)d_out;

    __nv_bfloat16 *xh, *xl, *wqh, *wql, *woh, *wol, *ohp, *olp;
    __nv_bfloat16 *qhp, *qlp, *khp, *klp, *vthp, *vtlp;
    float* vstp;
    cudaGetSymbolAddress((void**)&xh,  g_xh);
    cudaGetSymbolAddress((void**)&xl,  g_xl);
    cudaGetSymbolAddress((void**)&wqh, g_wqh);
    cudaGetSymbolAddress((void**)&wql, g_wql);
    cudaGetSymbolAddress((void**)&woh, g_woh);
    cudaGetSymbolAddress((void**)&wol, g_wol);
    cudaGetSymbolAddress((void**)&ohp, g_oh);
    cudaGetSymbolAddress((void**)&olp, g_ol);
    cudaGetSymbolAddress((void**)&qhp, g_qh);
    cudaGetSymbolAddress((void**)&qlp, g_ql);
    cudaGetSymbolAddress((void**)&khp, g_kh);
    cudaGetSymbolAddress((void**)&klp, g_kl);
    cudaGetSymbolAddress((void**)&vthp, g_vth);
    cudaGetSymbolAddress((void**)&vtlp, g_vtl);
    cudaGetSymbolAddress((void**)&vstp, g_vst);

    cudaFuncSetAttribute(mma_gemm_kernel, cudaFuncAttributeMaxDynamicSharedMemorySize,
                         GSMEM_BYTES);
    cudaFuncSetAttribute(attn_mma_kernel, cudaFuncAttributeMaxDynamicSharedMemorySize,
                         AT_SMEM);

    // 0) split inputs into hi/lo planes
    split_a_kernel<<<MROWS * 1024 / 256, 256>>>(x, xh, xl, MROWS * 1024);
    split_w_kernel<<<dim3(QKV_COLS / 32, 32), dim3(32, 8)>>>(wqkv, wqh, wql, QKV_COLS);
    split_w_kernel<<<dim3(DIM / 32, 32), dim3(32, 8)>>>(wout, woh, wol, DIM);

    // 1) qkv GEMM (fused 3-term split); epilogue: Q/K hi/lo + V fp32 staging
    mma_gemm_kernel<<<dim3(QKV_COLS / 128, MROWS / 128), 256, GSMEM_BYTES>>>(
        xh, xl, wqh, wql, nullptr, QKV_COLS, 1, qhp, qlp, khp, klp, vstp);

    // 1b) V transpose + split
    split_vt_kernel<<<dim3(SEQ / 32, 2, 32), dim3(32, 8)>>>(vstp, vthp, vtlp);

    // 2) flash attention; epilogue writes hi/lo planes for out-proj
    attn_mma_kernel<<<dim3(SEQ / 128, BATCH * HEADS), 256, AT_SMEM>>>(
        qhp, qlp, khp, klp, vthp, vtlp, smask, ohp, olp);

    // 3) out projection
    mma_gemm_kernel<<<dim3(DIM / 128, MROWS / 128), 256, GSMEM_BYTES>>>(
        ohp, olp, woh, wol, out, DIM, 0, nullptr, nullptr, nullptr, nullptr, nullptr);
}

// round 8
// speedup vs baseline: 1.0252x; 1.0252x over previous
#include <cuda_runtime.h>
#include <cuda_bf16.h>
#include <cstdint>
#include <math.h>

// Problem constants
#define BATCH 2
#define SEQ   2048
#define DIM   1024
#define HEADS 16
#define DHEAD 64
#define INNER 1024
#define QKV_COLS 3072
#define MROWS 4096              // BATCH*SEQ
#define ATT_SCALE 0.125f
#define LOG2E 1.4426950408889634f

// Scratch (device globals — no cudaMalloc allowed). hi/lo as separate planes.
__device__ __nv_bfloat16 g_xh [(size_t)MROWS * 1024];
__device__ __nv_bfloat16 g_xl [(size_t)MROWS * 1024];
__device__ __nv_bfloat16 g_wqh[(size_t)QKV_COLS * 1024];   // w_qkv^T hi
__device__ __nv_bfloat16 g_wql[(size_t)QKV_COLS * 1024];
__device__ __nv_bfloat16 g_woh[(size_t)DIM * 1024];        // w_out^T hi
__device__ __nv_bfloat16 g_wol[(size_t)DIM * 1024];
__device__ __nv_bfloat16 g_oh [(size_t)MROWS * 1024];      // attn out hi
__device__ __nv_bfloat16 g_ol [(size_t)MROWS * 1024];
__device__ __nv_bfloat16 g_qh [(size_t)MROWS * INNER];     // Q hi [b*n][h*64+d]
__device__ __nv_bfloat16 g_ql [(size_t)MROWS * INNER];
__device__ __nv_bfloat16 g_kh [(size_t)MROWS * INNER];
__device__ __nv_bfloat16 g_kl [(size_t)MROWS * INNER];
__device__ __nv_bfloat16 g_vth[(size_t)32 * 64 * SEQ];     // V^T hi [bh][d][n]
__device__ __nv_bfloat16 g_vtl[(size_t)32 * 64 * SEQ];
__device__ float g_vst[(size_t)MROWS * INNER];             // V fp32 staging

// ---------------------------------------------------------------------------
// PTX helpers (sm_80-compatible only; harness lowers via virtual compute_103)
// ---------------------------------------------------------------------------
__device__ __forceinline__ uint32_t smem_u32(const void* p) {
    uint32_t a;
    asm("{ .reg .u64 t; cvta.to.shared.u64 t, %1; cvt.u32.u64 %0, t; }"
        : "=r"(a) : "l"(p));
    return a;
}
#define SWZ128(o) ((o) ^ (((o) >> 3) & 0x70))
#define CP16(dst, src)  asm volatile("cp.async.cg.shared.global [%0], [%1], 16;" :: "r"(dst), "l"(src) : "memory")
#define CP_COMMIT()     asm volatile("cp.async.commit_group;" ::: "memory")
#define CP_WAIT1()      asm volatile("cp.async.wait_group 1;" ::: "memory")
#define CP_WAIT0()      asm volatile("cp.async.wait_group 0;" ::: "memory")

#define LDSM4(r0, r1, r2, r3, addr) \
    asm volatile("ldmatrix.sync.aligned.m8n8.x4.shared.b16 {%0,%1,%2,%3}, [%4];" \
                 : "=r"(r0), "=r"(r1), "=r"(r2), "=r"(r3) : "r"(addr))

#define MMA16816(d, a, b0, b1) \
    asm volatile("mma.sync.aligned.m16n8k16.row.col.f32.bf16.bf16.f32 " \
                 "{%0,%1,%2,%3}, {%4,%5,%6,%7}, {%8,%9}, {%0,%1,%2,%3};" \
                 : "+f"((d)[0]), "+f"((d)[1]), "+f"((d)[2]), "+f"((d)[3]) \
                 : "r"((a)[0]), "r"((a)[1]), "r"((a)[2]), "r"((a)[3]), \
                   "r"(b0), "r"(b1))

__device__ __forceinline__ uint32_t packbf(float lo, float hi) {
    uint32_t r;
    asm("cvt.rn.bf16x2.f32 %0, %1, %2;" : "=r"(r) : "f"(hi), "f"(lo));
    return r;
}
__device__ __forceinline__ void split2(float v0, float v1,
                                       uint32_t& hi, uint32_t& lo) {
    hi = packbf(v0, v1);
    float h0 = __uint_as_float(hi << 16);
    float h1 = __uint_as_float(hi & 0xffff0000u);
    lo = packbf(v0 - h0, v1 - h1);
}

// ---------------------------------------------------------------------------
// Input split kernels
// ---------------------------------------------------------------------------
__global__ void split_a_kernel(const float* __restrict__ in,
                               __nv_bfloat16* __restrict__ oh,
                               __nv_bfloat16* __restrict__ ol, int n)
{
    int idx = blockIdx.x * 256 + threadIdx.x;
    if (idx >= n) return;
    float v = in[idx];
    __nv_bfloat16 hi = __float2bfloat16(v);
    oh[idx] = hi;
    ol[idx] = __float2bfloat16(v - __bfloat162float(hi));
}

// Weights [1024 x N] -> transposed hi/lo [N x 1024]
__global__ void split_w_kernel(const float* __restrict__ w,
                               __nv_bfloat16* __restrict__ wh,
                               __nv_bfloat16* __restrict__ wl, int N)
{
    __shared__ float t[32][33];
    int bk = blockIdx.y * 32, bn = blockIdx.x * 32;
    int tx = threadIdx.x, ty = threadIdx.y;   // (32, 8)
#pragma unroll
    for (int i = 0; i < 4; i++)
        t[ty + 8 * i][tx] = w[(size_t)(bk + ty + 8 * i) * N + bn + tx];
    __syncthreads();
#pragma unroll
    for (int i = 0; i < 4; i++) {
        int n = bn + ty + 8 * i, k = bk + tx;
        float v = t[tx][ty + 8 * i];
        __nv_bfloat16 hi = __float2bfloat16(v);
        size_t o = (size_t)n * 1024 + k;
        wh[o] = hi;
        wl[o] = __float2bfloat16(v - __bfloat162float(hi));
    }
}

// V fp32 staging [b*n][h*64+d] -> V^T hi/lo [bh][d][n]
__global__ void split_vt_kernel(const float* __restrict__ vst,
                                __nv_bfloat16* __restrict__ vth,
                                __nv_bfloat16* __restrict__ vtl)
{
    __shared__ float t[32][33];
    int bh = blockIdx.z, b = bh >> 4, h = bh & 15;
    int n0 = blockIdx.x * 32, d0 = blockIdx.y * 32;
    int tx = threadIdx.x, ty = threadIdx.y;   // (32, 8)
#pragma unroll
    for (int i = 0; i < 4; i++)
        t[ty + 8 * i][tx] =
            vst[(size_t)(b * SEQ + n0 + ty + 8 * i) * 1024 + h * 64 + d0 + tx];
    __syncthreads();
#pragma unroll
    for (int i = 0; i < 4; i++) {
        int d = d0 + ty + 8 * i;
        float v = t[tx][ty + 8 * i];
        __nv_bfloat16 hi = __float2bfloat16(v);
        __nv_bfloat16 lo = __float2bfloat16(v - __bfloat162float(hi));
        size_t o = (size_t)(bh * 64 + d) * SEQ + n0 + tx;
        vth[o] = hi; vtl[o] = lo;
    }
}

// ---------------------------------------------------------------------------
// Fused-split bf16 GEMM: C = AhBh + AlBh + AhBl, fp32 acc. Term-major MMA
// ordering (dependency distance 16 per accumulator).
// K=1024, chunk k=32 (NCHUNK 32), 3-stage cp.async, 128x128 tile, 256 thr.
// ---------------------------------------------------------------------------
#define STAGE2 32768
#define GSMEM_BYTES (3 * STAGE2)
#define NCHUNK 32

__device__ __forceinline__ void gemm_load_chunk(
    uint32_t sb, int stage, int chunk, int tid,
    const __nv_bfloat16* __restrict__ Ah, const __nv_bfloat16* __restrict__ Al,
    const __nv_bfloat16* __restrict__ Bh, const __nv_bfloat16* __restrict__ Bl,
    int row0, int col0)
{
    uint32_t sA = sb + stage * STAGE2;
    uint32_t sB = sA + 16384;
    int k0 = chunk * 32;
#pragma unroll
    for (int i = 0; i < 4; i++) {
        int g = tid + i * 256;          // 0..1023
        int row = g >> 3, c16 = g & 7;  // granules 0-3: hi, 4-7: lo
        uint32_t off = SWZ128((uint32_t)(row * 128 + c16 * 16));
        const __nv_bfloat16* a = (c16 < 4) ? Ah : Al;
        const __nv_bfloat16* b = (c16 < 4) ? Bh : Bl;
        int kk = k0 + (c16 & 3) * 8;
        CP16(sA + off, a + (size_t)(row0 + row) * 1024 + kk);
        CP16(sB + off, b + (size_t)(col0 + row) * 1024 + kk);
    }
}

__global__ __launch_bounds__(256, 2)
void mma_gemm_kernel(const __nv_bfloat16* __restrict__ Ah,
                     const __nv_bfloat16* __restrict__ Al,
                     const __nv_bfloat16* __restrict__ Bh,
                     const __nv_bfloat16* __restrict__ Bl,
                     float* __restrict__ C, int N, int mode,
                     __nv_bfloat16* __restrict__ qh, __nv_bfloat16* __restrict__ ql,
                     __nv_bfloat16* __restrict__ kh, __nv_bfloat16* __restrict__ kl,
                     float* __restrict__ vst)
{
    extern __shared__ char smem[];
    uint32_t sb = smem_u32(smem);
    const int tid  = threadIdx.x;
    const int lane = tid & 31;
    const int wid  = tid >> 5;
    const int wm   = wid & 3;
    const int wn   = wid >> 2;
    const int row0 = blockIdx.y * 128;
    const int col0 = blockIdx.x * 128;

    float acc[2][8][4];
#pragma unroll
    for (int mt = 0; mt < 2; mt++)
#pragma unroll
        for (int nt = 0; nt < 8; nt++)
#pragma unroll
            for (int v = 0; v < 4; v++) acc[mt][nt][v] = 0.0f;

    gemm_load_chunk(sb, 0, 0, tid, Ah, Al, Bh, Bl, row0, col0);
    CP_COMMIT();
    gemm_load_chunk(sb, 1, 1, tid, Ah, Al, Bh, Bl, row0, col0);
    CP_COMMIT();

    const int arow_l = wm * 32 + (lane & 15);
    const int brow_l = wn * 64 + (lane & 15);
    const int khalf  = (lane >> 4) * 16;

    for (int c = 0; c < NCHUNK; c++) {
        CP_WAIT1();
        __syncthreads();

        int nc = c + 2;
        if (nc < NCHUNK)
            gemm_load_chunk(sb, nc % 3, nc, tid, Ah, Al, Bh, Bl, row0, col0);
        CP_COMMIT();

        uint32_t sA = sb + (c % 3) * STAGE2;
        uint32_t sB = sA + 16384;

#pragma unroll
        for (int ks = 0; ks < 2; ks++) {
            const uint32_t kb = (uint32_t)(ks * 32 + khalf);
            uint32_t ah[2][4], al2[2][4], bb[4][4];
#pragma unroll
            for (int mt = 0; mt < 2; mt++) {
                uint32_t rb = (uint32_t)((arow_l + mt * 16) * 128);
                LDSM4(ah[mt][0], ah[mt][1], ah[mt][2], ah[mt][3],
                      sA + SWZ128(rb + kb));
                LDSM4(al2[mt][0], al2[mt][1], al2[mt][2], al2[mt][3],
                      sA + SWZ128(rb + 64 + kb));
            }
            // -- Wh fragments --
#pragma unroll
            for (int np = 0; np < 4; np++)
                LDSM4(bb[np][0], bb[np][1], bb[np][2], bb[np][3],
                      sB + SWZ128((uint32_t)((brow_l + np * 16) * 128) + kb));
            // term 1: Ah*Wh (all 16 accs)
#pragma unroll
            for (int mt = 0; mt < 2; mt++)
#pragma unroll
                for (int nt = 0; nt < 8; nt++) {
                    int np = nt >> 1, sel = nt & 1;
                    MMA16816(acc[mt][nt], ah[mt], bb[np][sel], bb[np][2 + sel]);
                }
            // term 2: Al*Wh (distance 16 from term 1)
#pragma unroll
            for (int mt = 0; mt < 2; mt++)
#pragma unroll
                for (int nt = 0; nt < 8; nt++) {
                    int np = nt >> 1, sel = nt & 1;
                    MMA16816(acc[mt][nt], al2[mt], bb[np][sel], bb[np][2 + sel]);
                }
            // -- Wl fragments --
#pragma unroll
            for (int np = 0; np < 4; np++)
                LDSM4(bb[np][0], bb[np][1], bb[np][2], bb[np][3],
                      sB + SWZ128((uint32_t)((brow_l + np * 16) * 128) + 64 + kb));
            // term 3: Ah*Wl
#pragma unroll
            for (int mt = 0; mt < 2; mt++)
#pragma unroll
                for (int nt = 0; nt < 8; nt++) {
                    int np = nt >> 1, sel = nt & 1;
                    MMA16816(acc[mt][nt], ah[mt], bb[np][sel], bb[np][2 + sel]);
                }
        }
    }

    const int g = lane >> 2, t = lane & 3;
#pragma unroll
    for (int mt = 0; mt < 2; mt++) {
        int r0 = row0 + wm * 32 + mt * 16 + g;
#pragma unroll
        for (int nt = 0; nt < 8; nt++) {
            int col = col0 + wn * 64 + nt * 8 + t * 2;
            if (mode == 0) {
                *(float2*)&C[(size_t)r0 * N + col] =
                    make_float2(acc[mt][nt][0], acc[mt][nt][1]);
                *(float2*)&C[(size_t)(r0 + 8) * N + col] =
                    make_float2(acc[mt][nt][2], acc[mt][nt][3]);
            } else {
                int sec = col >> 10, cc = col & 1023;
                if (sec == 2) {
                    *(float2*)&vst[(size_t)r0 * 1024 + cc] =
                        make_float2(acc[mt][nt][0], acc[mt][nt][1]);
                    *(float2*)&vst[(size_t)(r0 + 8) * 1024 + cc] =
                        make_float2(acc[mt][nt][2], acc[mt][nt][3]);
                } else {
                    __nv_bfloat16* dh = sec ? kh : qh;
                    __nv_bfloat16* dl = sec ? kl : ql;
                    uint32_t hi, lo;
                    split2(acc[mt][nt][0], acc[mt][nt][1], hi, lo);
                    *(uint32_t*)&dh[(size_t)r0 * 1024 + cc] = hi;
                    *(uint32_t*)&dl[(size_t)r0 * 1024 + cc] = lo;
                    split2(acc[mt][nt][2], acc[mt][nt][3], hi, lo);
                    *(uint32_t*)&dh[(size_t)(r0 + 8) * 1024 + cc] = hi;
                    *(uint32_t*)&dl[(size_t)(r0 + 8) * 1024 + cc] = lo;
                }
            }
        }
    }
}

// ---------------------------------------------------------------------------
// Flash attention on mma.sync bf16, register-resident Q and P, j-tile 64,
// 2 CTAs/SM. Term-major MMA ordering (distance 8 per accumulator).
// SMEM: QH 0, QL 16384; stages s=0,1 at 32768+s*32768:
//       KH+0, KL+8192, VH+16384, VL+24576 (all 128B rows);
//       MASK 98304 + s*256. Total 98816.
// ---------------------------------------------------------------------------
#define AT_QH   0
#define AT_QL   16384
#define AT_STG  32768
#define AT_KH   0
#define AT_KL   8192
#define AT_VH   16384
#define AT_VL   24576
#define AT_MASK 98304
#define AT_SMEM 98816

__device__ __forceinline__ void attn_load_stage(
    uint32_t sb, int stage, int j0, int tid, int b, int bh,
    const __nv_bfloat16* __restrict__ kh, const __nv_bfloat16* __restrict__ kl,
    const __nv_bfloat16* __restrict__ vth, const __nv_bfloat16* __restrict__ vtl,
    const float* __restrict__ mask)
{
    uint32_t st = sb + AT_STG + stage * 32768;
    const int h = bh & 15;
    const __nv_bfloat16* khg = kh + (size_t)(b * SEQ + j0) * 1024 + h * 64;
    const __nv_bfloat16* klg = kl + (size_t)(b * SEQ + j0) * 1024 + h * 64;
#pragma unroll
    for (int i = 0; i < 2; i++) {
        int t = tid + i * 256;          // 0..511
        int row = t >> 3, c = t & 7;
        uint32_t off = SWZ128((uint32_t)(row * 128 + c * 16));
        CP16(st + AT_KH + off, khg + (size_t)row * 1024 + c * 8);
        CP16(st + AT_KL + off, klg + (size_t)row * 1024 + c * 8);
    }
    const __nv_bfloat16* vhg = vth + (size_t)(bh * 64) * SEQ + j0;
    const __nv_bfloat16* vlg = vtl + (size_t)(bh * 64) * SEQ + j0;
#pragma unroll
    for (int i = 0; i < 2; i++) {
        int t = tid + i * 256;          // 0..511
        int d = t >> 3, c = t & 7;
        uint32_t off = SWZ128((uint32_t)(d * 128 + c * 16));
        CP16(st + AT_VH + off, vhg + (size_t)d * SEQ + c * 8);
        CP16(st + AT_VL + off, vlg + (size_t)d * SEQ + c * 8);
    }
    if (tid < 16)
        CP16(sb + AT_MASK + stage * 256 + tid * 16, mask + b * SEQ + j0 + tid * 4);
}

__global__ __launch_bounds__(256, 2)
void attn_mma_kernel(const __nv_bfloat16* __restrict__ qh,
                     const __nv_bfloat16* __restrict__ ql,
                     const __nv_bfloat16* __restrict__ kh,
                     const __nv_bfloat16* __restrict__ kl,
                     const __nv_bfloat16* __restrict__ vth,
                     const __nv_bfloat16* __restrict__ vtl,
                     const float* __restrict__ mask,
                     __nv_bfloat16* __restrict__ oh,
                     __nv_bfloat16* __restrict__ ol)
{
    extern __shared__ char smem[];
    uint32_t sb = smem_u32(smem);
    const int tid = threadIdx.x, lane = tid & 31, w = tid >> 5;
    const int g = lane >> 2, t4 = lane & 3;
    const int l16 = lane & 15, khalf = (lane >> 4) * 16;
    const int bh = blockIdx.y, b = bh >> 4, h = bh & 15;
    const int i0 = blockIdx.x * 128;

    // async-load Q tile (hi+lo) as its own commit group
    {
        const __nv_bfloat16* qhg = qh + (size_t)(b * SEQ + i0) * 1024 + h * 64;
        const __nv_bfloat16* qlg = ql + (size_t)(b * SEQ + i0) * 1024 + h * 64;
#pragma unroll
        for (int i = 0; i < 4; i++) {
            int t = tid + i * 256;
            int row = t >> 3, c = t & 7;
            uint32_t off = SWZ128((uint32_t)(row * 128 + c * 16));
            CP16(sb + AT_QH + off, qhg + (size_t)row * 1024 + c * 8);
            CP16(sb + AT_QL + off, qlg + (size_t)row * 1024 + c * 8);
        }
    }
    CP_COMMIT();
    attn_load_stage(sb, 0, 0, tid, b, bh, kh, kl, vth, vtl, mask);
    CP_COMMIT();

    // Q fragments -> registers
    CP_WAIT1();
    __syncthreads();
    uint32_t qfh[4][4], qfl[4][4];
    const uint32_t qrow = (uint32_t)((w * 16 + l16) * 128);
#pragma unroll
    for (int ks = 0; ks < 4; ks++) {
        uint32_t kb = (uint32_t)(ks * 32 + khalf);
        LDSM4(qfh[ks][0], qfh[ks][1], qfh[ks][2], qfh[ks][3],
              sb + AT_QH + SWZ128(qrow + kb));
        LDSM4(qfl[ks][0], qfl[ks][1], qfl[ks][2], qfl[ks][3],
              sb + AT_QL + SWZ128(qrow + kb));
    }

    float m0 = -1e30f, m1 = -1e30f, lsum0 = 0.0f, lsum1 = 0.0f;
    float o[8][4];
#pragma unroll
    for (int nt = 0; nt < 8; nt++)
#pragma unroll
        for (int v = 0; v < 4; v++) o[nt][v] = 0.0f;

    const float MSC = ATT_SCALE * LOG2E;   // logits in log2 domain

    for (int jt = 0; jt < 32; jt++) {
        CP_WAIT0();
        __syncthreads();
        if (jt + 1 < 32)
            attn_load_stage(sb, (jt + 1) & 1, (jt + 1) * 64, tid, b, bh,
                            kh, kl, vth, vtl, mask);
        CP_COMMIT();

        uint32_t stg = sb + AT_STG + (jt & 1) * 32768;
        const float* maskS = (const float*)(smem + AT_MASK + (jt & 1) * 256);

        // ---- S = Q K^T : term-major (Qh*Kh all, Ql*Kh all, Qh*Kl all) ----
        float s[8][4];
#pragma unroll
        for (int nt = 0; nt < 8; nt++)
#pragma unroll
            for (int v = 0; v < 4; v++) s[nt][v] = 0.0f;

#pragma unroll
        for (int ks = 0; ks < 4; ks++) {
            const uint32_t kb = (uint32_t)(ks * 32 + khalf);
            uint32_t b4[4][4];
#pragma unroll
            for (int np = 0; np < 4; np++)
                LDSM4(b4[np][0], b4[np][1], b4[np][2], b4[np][3],
                      stg + AT_KH + SWZ128((uint32_t)((np * 16 + l16) * 128) + kb));
#pragma unroll
            for (int np = 0; np < 4; np++) {
                MMA16816(s[np * 2],     qfh[ks], b4[np][0], b4[np][2]);
                MMA16816(s[np * 2 + 1], qfh[ks], b4[np][1], b4[np][3]);
            }
#pragma unroll
            for (int np = 0; np < 4; np++) {
                MMA16816(s[np * 2],     qfl[ks], b4[np][0], b4[np][2]);
                MMA16816(s[np * 2 + 1], qfl[ks], b4[np][1], b4[np][3]);
            }
        }
#pragma unroll
        for (int ks = 0; ks < 4; ks++) {
            const uint32_t kb = (uint32_t)(ks * 32 + khalf);
            uint32_t b4[4][4];
#pragma unroll
            for (int np = 0; np < 4; np++)
                LDSM4(b4[np][0], b4[np][1], b4[np][2], b4[np][3],
                      stg + AT_KL + SWZ128((uint32_t)((np * 16 + l16) * 128) + kb));
#pragma unroll
            for (int np = 0; np < 4; np++) {
                MMA16816(s[np * 2],     qfh[ks], b4[np][0], b4[np][2]);
                MMA16816(s[np * 2 + 1], qfh[ks], b4[np][1], b4[np][3]);
            }
        }

        // ---- mask*scale*log2e, online softmax (log2 domain) ----
        float rm0 = -1e30f, rm1 = -1e30f;
#pragma unroll
        for (int nt = 0; nt < 8; nt++) {
            float2 mk = *(const float2*)&maskS[nt * 8 + t4 * 2];
            mk.x *= MSC; mk.y *= MSC;
            s[nt][0] *= mk.x; s[nt][1] *= mk.y;
            s[nt][2] *= mk.x; s[nt][3] *= mk.y;
            rm0 = fmaxf(rm0, fmaxf(s[nt][0], s[nt][1]));
            rm1 = fmaxf(rm1, fmaxf(s[nt][2], s[nt][3]));
        }
        rm0 = fmaxf(rm0, __shfl_xor_sync(0xffffffffu, rm0, 1));
        rm0 = fmaxf(rm0, __shfl_xor_sync(0xffffffffu, rm0, 2));
        rm1 = fmaxf(rm1, __shfl_xor_sync(0xffffffffu, rm1, 1));
        rm1 = fmaxf(rm1, __shfl_xor_sync(0xffffffffu, rm1, 2));
        float mn0 = fmaxf(m0, rm0), mn1 = fmaxf(m1, rm1);
        float al0 = exp2f(m0 - mn0), al1 = exp2f(m1 - mn1);
        m0 = mn0; m1 = mn1;
        lsum0 *= al0; lsum1 *= al1;
#pragma unroll
        for (int nt = 0; nt < 8; nt++) {
            o[nt][0] *= al0; o[nt][1] *= al0;
            o[nt][2] *= al1; o[nt][3] *= al1;
        }
        float ps0 = 0.0f, ps1 = 0.0f;
#pragma unroll
        for (int nt = 0; nt < 8; nt++) {
            s[nt][0] = exp2f(s[nt][0] - m0);
            s[nt][1] = exp2f(s[nt][1] - m0);
            s[nt][2] = exp2f(s[nt][2] - m1);
            s[nt][3] = exp2f(s[nt][3] - m1);
            ps0 += s[nt][0] + s[nt][1];
            ps1 += s[nt][2] + s[nt][3];
        }
        lsum0 += ps0; lsum1 += ps1;

        // ---- pack P fragments (S accum frag == A operand frag layout) ----
        uint32_t ph[4][4], pl[4][4];
#pragma unroll
        for (int ks = 0; ks < 4; ks++) {
            split2(s[2 * ks][0],     s[2 * ks][1],     ph[ks][0], pl[ks][0]);
            split2(s[2 * ks][2],     s[2 * ks][3],     ph[ks][1], pl[ks][1]);
            split2(s[2 * ks + 1][0], s[2 * ks + 1][1], ph[ks][2], pl[ks][2]);
            split2(s[2 * ks + 1][2], s[2 * ks + 1][3], ph[ks][3], pl[ks][3]);
        }

        // ---- O += P V : term-major (Ph*Vh all, Pl*Vh all, Ph*Vl all) ----
#pragma unroll
        for (int ks = 0; ks < 4; ks++) {
            const uint32_t kb = (uint32_t)(ks * 32 + khalf);
            uint32_t b4[4][4];
#pragma unroll
            for (int np = 0; np < 4; np++)
                LDSM4(b4[np][0], b4[np][1], b4[np][2], b4[np][3],
                      stg + AT_VH + SWZ128((uint32_t)((np * 16 + l16) * 128) + kb));
#pragma unroll
            for (int np = 0; np < 4; np++) {
                MMA16816(o[np * 2],     ph[ks], b4[np][0], b4[np][2]);
                MMA16816(o[np * 2 + 1], ph[ks], b4[np][1], b4[np][3]);
            }
#pragma unroll
            for (int np = 0; np < 4; np++) {
                MMA16816(o[np * 2],     pl[ks], b4[np][0], b4[np][2]);
                MMA16816(o[np * 2 + 1], pl[ks], b4[np][1], b4[np][3]);
            }
        }
#pragma unroll
        for (int ks = 0; ks < 4; ks++) {
            const uint32_t kb = (uint32_t)(ks * 32 + khalf);
            uint32_t b4[4][4];
#pragma unroll
            for (int np = 0; np < 4; np++)
                LDSM4(b4[np][0], b4[np][1], b4[np][2], b4[np][3],
                      stg + AT_VL + SWZ128((uint32_t)((np * 16 + l16) * 128) + kb));
#pragma unroll
            for (int np = 0; np < 4; np++) {
                MMA16816(o[np * 2],     ph[ks], b4[np][0], b4[np][2]);
                MMA16816(o[np * 2 + 1], ph[ks], b4[np][1], b4[np][3]);
            }
        }
    }

    // ---- finalize: reduce l over quad, normalize, write hi/lo planes ----
    lsum0 += __shfl_xor_sync(0xffffffffu, lsum0, 1);
    lsum0 += __shfl_xor_sync(0xffffffffu, lsum0, 2);
    lsum1 += __shfl_xor_sync(0xffffffffu, lsum1, 1);
    lsum1 += __shfl_xor_sync(0xffffffffu, lsum1, 2);
    float inv0 = 1.0f / lsum0, inv1 = 1.0f / lsum1;

    const int r0 = i0 + w * 16 + g, r1 = r0 + 8;
#pragma unroll
    for (int nt = 0; nt < 8; nt++) {
        int col = nt * 8 + t4 * 2;
        uint32_t hi, lo;
        size_t base0 = (size_t)(b * SEQ + r0) * 1024 + h * 64 + col;
        split2(o[nt][0] * inv0, o[nt][1] * inv0, hi, lo);
        *(uint32_t*)&oh[base0] = hi;
        *(uint32_t*)&ol[base0] = lo;
        size_t base1 = (size_t)(b * SEQ + r1) * 1024 + h * 64 + col;
        split2(o[nt][2] * inv1, o[nt][3] * inv1, hi, lo);
        *(uint32_t*)&oh[base1] = hi;
        *(uint32_t*)&ol[base1] = lo;
    }
}

// ---------------------------------------------------------------------------
// Launch
// ---------------------------------------------------------------------------
extern "C" void kernel_launch(void* const* d_in, const int* in_sizes, int n_in,
                              void* d_out, int out_size)
{
    const float* x     = (const float*)d_in[0];
    const float* smask = (const float*)d_in[1];
    const float* wqkv  = (const float*)d_in[2];
    const float* wout  = (const float*)d_in[3];
    float* out = (float*)d_out;

    __nv_bfloat16 *xh, *xl, *wqh, *wql, *woh, *wol, *ohp, *olp;
    __nv_bfloat16 *qhp, *qlp, *khp, *klp, *vthp, *vtlp;
    float* vstp;
    cudaGetSymbolAddress((void**)&xh,  g_xh);
    cudaGetSymbolAddress((void**)&xl,  g_xl);
    cudaGetSymbolAddress((void**)&wqh, g_wqh);
    cudaGetSymbolAddress((void**)&wql, g_wql);
    cudaGetSymbolAddress((void**)&woh, g_woh);
    cudaGetSymbolAddress((void**)&wol, g_wol);
    cudaGetSymbolAddress((void**)&ohp, g_oh);
    cudaGetSymbolAddress((void**)&olp, g_ol);
    cudaGetSymbolAddress((void**)&qhp, g_qh);
    cudaGetSymbolAddress((void**)&qlp, g_ql);
    cudaGetSymbolAddress((void**)&khp, g_kh);
    cudaGetSymbolAddress((void**)&klp, g_kl);
    cudaGetSymbolAddress((void**)&vthp, g_vth);
    cudaGetSymbolAddress((void**)&vtlp, g_vtl);
    cudaGetSymbolAddress((void**)&vstp, g_vst);

    cudaFuncSetAttribute(mma_gemm_kernel, cudaFuncAttributeMaxDynamicSharedMemorySize,
                         GSMEM_BYTES);
    cudaFuncSetAttribute(attn_mma_kernel, cudaFuncAttributeMaxDynamicSharedMemorySize,
                         AT_SMEM);

    // 0) split inputs into hi/lo planes
    split_a_kernel<<<MROWS * 1024 / 256, 256>>>(x, xh, xl, MROWS * 1024);
    split_w_kernel<<<dim3(QKV_COLS / 32, 32), dim3(32, 8)>>>(wqkv, wqh, wql, QKV_COLS);
    split_w_kernel<<<dim3(DIM / 32, 32), dim3(32, 8)>>>(wout, woh, wol, DIM);

    // 1) qkv GEMM (fused 3-term split); epilogue: Q/K hi/lo + V fp32 staging
    mma_gemm_kernel<<<dim3(QKV_COLS / 128, MROWS / 128), 256, GSMEM_BYTES>>>(
        xh, xl, wqh, wql, nullptr, QKV_COLS, 1, qhp, qlp, khp, klp, vstp);

    // 1b) V transpose + split
    split_vt_kernel<<<dim3(SEQ / 32, 2, 32), dim3(32, 8)>>>(vstp, vthp, vtlp);

    // 2) flash attention; epilogue writes hi/lo planes for out-proj
    attn_mma_kernel<<<dim3(SEQ / 128, BATCH * HEADS), 256, AT_SMEM>>>(
        qhp, qlp, khp, klp, vthp, vtlp, smask, ohp, olp);

    // 3) out projection
    mma_gemm_kernel<<<dim3(DIM / 128, MROWS / 128), 256, GSMEM_BYTES>>>(
        ohp, olp, woh, wol, out, DIM, 0, nullptr, nullptr, nullptr, nullptr, nullptr);
}

// round 9
// speedup vs baseline: 1.4131x; 1.3784x over previous
#include <cuda_runtime.h>
#include <cuda_fp16.h>
#include <cstdint>
#include <math.h>

// Problem constants
#define BATCH 2
#define SEQ   2048
#define DIM   1024
#define HEADS 16
#define DHEAD 64
#define INNER 1024
#define QKV_COLS 3072
#define MROWS 4096              // BATCH*SEQ
#define ATT_SCALE 0.125f
#define LOG2E 1.4426950408889634f

// Scratch (device globals — no cudaMalloc allowed).
// fp16 2-term split: activations carry hi+lo planes, weights/K/V single plane.
__device__ __half g_xh [(size_t)MROWS * 1024];
__device__ __half g_xl [(size_t)MROWS * 1024];
__device__ __half g_wq [(size_t)QKV_COLS * 1024];   // w_qkv^T fp16
__device__ __half g_wo [(size_t)DIM * 1024];        // w_out^T fp16
__device__ __half g_oh [(size_t)MROWS * 1024];      // attn out hi
__device__ __half g_ol [(size_t)MROWS * 1024];
__device__ __half g_qh [(size_t)MROWS * INNER];     // Q hi [b*n][h*64+d]
__device__ __half g_ql [(size_t)MROWS * INNER];
__device__ __half g_k  [(size_t)MROWS * INNER];     // K fp16 single
__device__ __half g_vt [(size_t)32 * 64 * SEQ];     // V^T fp16 [bh][d][n]
__device__ float g_vst[(size_t)MROWS * INNER];      // V fp32 staging

// ---------------------------------------------------------------------------
// PTX helpers (sm_80-compatible only; harness lowers via virtual compute_103)
// ---------------------------------------------------------------------------
__device__ __forceinline__ uint32_t smem_u32(const void* p) {
    uint32_t a;
    asm("{ .reg .u64 t; cvta.to.shared.u64 t, %1; cvt.u32.u64 %0, t; }"
        : "=r"(a) : "l"(p));
    return a;
}
#define SWZ128(o) ((o) ^ (((o) >> 3) & 0x70))
#define CP16(dst, src)  asm volatile("cp.async.cg.shared.global [%0], [%1], 16;" :: "r"(dst), "l"(src) : "memory")
#define CP_COMMIT()     asm volatile("cp.async.commit_group;" ::: "memory")
#define CP_WAIT1()      asm volatile("cp.async.wait_group 1;" ::: "memory")
#define CP_WAIT0()      asm volatile("cp.async.wait_group 0;" ::: "memory")

#define LDSM4(r0, r1, r2, r3, addr) \
    asm volatile("ldmatrix.sync.aligned.m8n8.x4.shared.b16 {%0,%1,%2,%3}, [%4];" \
                 : "=r"(r0), "=r"(r1), "=r"(r2), "=r"(r3) : "r"(addr))

#define MMA16816(d, a, b0, b1) \
    asm volatile("mma.sync.aligned.m16n8k16.row.col.f32.f16.f16.f32 " \
                 "{%0,%1,%2,%3}, {%4,%5,%6,%7}, {%8,%9}, {%0,%1,%2,%3};" \
                 : "+f"((d)[0]), "+f"((d)[1]), "+f"((d)[2]), "+f"((d)[3]) \
                 : "r"((a)[0]), "r"((a)[1]), "r"((a)[2]), "r"((a)[3]), \
                   "r"(b0), "r"(b1))

// split two fp32 -> packed fp16 hi-pair / lo-pair
__device__ __forceinline__ void split2h(float v0, float v1,
                                        uint32_t& hi, uint32_t& lo) {
    __half2 h = __floats2half2_rn(v0, v1);
    float2 hf = __half22float2(h);
    __half2 l = __floats2half2_rn(v0 - hf.x, v1 - hf.y);
    hi = *(uint32_t*)&h;
    lo = *(uint32_t*)&l;
}
__device__ __forceinline__ uint32_t packh(float v0, float v1) {
    __half2 h = __floats2half2_rn(v0, v1);
    return *(uint32_t*)&h;
}

// ---------------------------------------------------------------------------
// Input split kernels
// ---------------------------------------------------------------------------
__global__ void split_a_kernel(const float* __restrict__ in,
                               __half* __restrict__ oh,
                               __half* __restrict__ ol, int n)
{
    int idx = blockIdx.x * 256 + threadIdx.x;
    if (idx >= n) return;
    float v = in[idx];
    __half hi = __float2half_rn(v);
    oh[idx] = hi;
    ol[idx] = __float2half_rn(v - __half2float(hi));
}

// Weights [1024 x N] -> transposed fp16 [N x 1024]
__global__ void split_w_kernel(const float* __restrict__ w,
                               __half* __restrict__ wh, int N)
{
    __shared__ float t[32][33];
    int bk = blockIdx.y * 32, bn = blockIdx.x * 32;
    int tx = threadIdx.x, ty = threadIdx.y;   // (32, 8)
#pragma unroll
    for (int i = 0; i < 4; i++)
        t[ty + 8 * i][tx] = w[(size_t)(bk + ty + 8 * i) * N + bn + tx];
    __syncthreads();
#pragma unroll
    for (int i = 0; i < 4; i++) {
        int n = bn + ty + 8 * i, k = bk + tx;
        wh[(size_t)n * 1024 + k] = __float2half_rn(t[tx][ty + 8 * i]);
    }
}

// V fp32 staging [b*n][h*64+d] -> V^T fp16 [bh][d][n]
__global__ void split_vt_kernel(const float* __restrict__ vst,
                                __half* __restrict__ vt)
{
    __shared__ float t[32][33];
    int bh = blockIdx.z, b = bh >> 4, h = bh & 15;
    int n0 = blockIdx.x * 32, d0 = blockIdx.y * 32;
    int tx = threadIdx.x, ty = threadIdx.y;   // (32, 8)
#pragma unroll
    for (int i = 0; i < 4; i++)
        t[ty + 8 * i][tx] =
            vst[(size_t)(b * SEQ + n0 + ty + 8 * i) * 1024 + h * 64 + d0 + tx];
    __syncthreads();
#pragma unroll
    for (int i = 0; i < 4; i++) {
        int d = d0 + ty + 8 * i;
        vt[(size_t)(bh * 64 + d) * SEQ + n0 + tx] =
            __float2half_rn(t[tx][ty + 8 * i]);
    }
}

// ---------------------------------------------------------------------------
// 2-term fp16 GEMM: C = Ah*B + Al*B (= A_exact * fp16(B)), fp32 accumulate.
// K=1024, chunk k=64 (NCHUNK 16), 2-stage cp.async, 128x128 tile, 256 thr.
// Stage 48KB: AH 16KB (128r x 128B) | AL +16384 | BH +32768.
// ---------------------------------------------------------------------------
#define GST 49152
#define GSMEM_BYTES (2 * GST)
#define NCHUNK 16

__device__ __forceinline__ void gemm_load_chunk(
    uint32_t sb, int stage, int chunk, int tid,
    const __half* __restrict__ Ah, const __half* __restrict__ Al,
    const __half* __restrict__ Bh, int row0, int col0)
{
    uint32_t base = sb + stage * GST;
    int k0 = chunk * 64;
#pragma unroll
    for (int i = 0; i < 4; i++) {
        int g = tid + i * 256;          // 0..1023
        int row = g >> 3, c = g & 7;
        uint32_t off = SWZ128((uint32_t)(row * 128 + c * 16));
        size_t ao = (size_t)(row0 + row) * 1024 + k0 + c * 8;
        CP16(base + off,         Ah + ao);
        CP16(base + 16384 + off, Al + ao);
        CP16(base + 32768 + off, Bh + (size_t)(col0 + row) * 1024 + k0 + c * 8);
    }
}

__global__ __launch_bounds__(256, 2)
void mma_gemm_kernel(const __half* __restrict__ Ah,
                     const __half* __restrict__ Al,
                     const __half* __restrict__ Bh,
                     float* __restrict__ C, int N, int mode,
                     __half* __restrict__ qh, __half* __restrict__ ql,
                     __half* __restrict__ kk, float* __restrict__ vst)
{
    extern __shared__ char smem[];
    uint32_t sb = smem_u32(smem);
    const int tid  = threadIdx.x;
    const int lane = tid & 31;
    const int wid  = tid >> 5;
    const int wm   = wid & 3;
    const int wn   = wid >> 2;
    const int row0 = blockIdx.y * 128;
    const int col0 = blockIdx.x * 128;

    float acc[2][8][4];
#pragma unroll
    for (int mt = 0; mt < 2; mt++)
#pragma unroll
        for (int nt = 0; nt < 8; nt++)
#pragma unroll
            for (int v = 0; v < 4; v++) acc[mt][nt][v] = 0.0f;

    gemm_load_chunk(sb, 0, 0, tid, Ah, Al, Bh, row0, col0);
    CP_COMMIT();
    gemm_load_chunk(sb, 1, 1, tid, Ah, Al, Bh, row0, col0);
    CP_COMMIT();

    const int arow_l = wm * 32 + (lane & 15);
    const int brow_l = wn * 64 + (lane & 15);
    const int khalf  = (lane >> 4) * 16;

    for (int c = 0; c < NCHUNK; c++) {
        CP_WAIT1();              // chunk c resident
        __syncthreads();

        uint32_t sA  = sb + (c & 1) * GST;
        uint32_t sAl = sA + 16384;
        uint32_t sB  = sA + 32768;

#pragma unroll
        for (int ks = 0; ks < 4; ks++) {
            const uint32_t kb = (uint32_t)(ks * 32 + khalf);
            uint32_t ah[2][4], al2[2][4], bb[4][4];
#pragma unroll
            for (int mt = 0; mt < 2; mt++) {
                uint32_t rb = (uint32_t)((arow_l + mt * 16) * 128);
                LDSM4(ah[mt][0], ah[mt][1], ah[mt][2], ah[mt][3],
                      sA + SWZ128(rb + kb));
                LDSM4(al2[mt][0], al2[mt][1], al2[mt][2], al2[mt][3],
                      sAl + SWZ128(rb + kb));
            }
#pragma unroll
            for (int np = 0; np < 4; np++)
                LDSM4(bb[np][0], bb[np][1], bb[np][2], bb[np][3],
                      sB + SWZ128((uint32_t)((brow_l + np * 16) * 128) + kb));
            // term 1: Ah*B (all 16 accs)
#pragma unroll
            for (int mt = 0; mt < 2; mt++)
#pragma unroll
                for (int nt = 0; nt < 8; nt++) {
                    int np = nt >> 1, sel = nt & 1;
                    MMA16816(acc[mt][nt], ah[mt], bb[np][sel], bb[np][2 + sel]);
                }
            // term 2: Al*B (distance 16)
#pragma unroll
            for (int mt = 0; mt < 2; mt++)
#pragma unroll
                for (int nt = 0; nt < 8; nt++) {
                    int np = nt >> 1, sel = nt & 1;
                    MMA16816(acc[mt][nt], al2[mt], bb[np][sel], bb[np][2 + sel]);
                }
        }

        __syncthreads();         // all warps done with stage c&1
        if (c + 2 < NCHUNK)
            gemm_load_chunk(sb, c & 1, c + 2, tid, Ah, Al, Bh, row0, col0);
        CP_COMMIT();
    }

    const int g = lane >> 2, t = lane & 3;
#pragma unroll
    for (int mt = 0; mt < 2; mt++) {
        int r0 = row0 + wm * 32 + mt * 16 + g;
#pragma unroll
        for (int nt = 0; nt < 8; nt++) {
            int col = col0 + wn * 64 + nt * 8 + t * 2;
            if (mode == 0) {
                *(float2*)&C[(size_t)r0 * N + col] =
                    make_float2(acc[mt][nt][0], acc[mt][nt][1]);
                *(float2*)&C[(size_t)(r0 + 8) * N + col] =
                    make_float2(acc[mt][nt][2], acc[mt][nt][3]);
            } else {
                int sec = col >> 10, cc = col & 1023;
                if (sec == 2) {
                    *(float2*)&vst[(size_t)r0 * 1024 + cc] =
                        make_float2(acc[mt][nt][0], acc[mt][nt][1]);
                    *(float2*)&vst[(size_t)(r0 + 8) * 1024 + cc] =
                        make_float2(acc[mt][nt][2], acc[mt][nt][3]);
                } else if (sec == 1) {
                    *(uint32_t*)&kk[(size_t)r0 * 1024 + cc] =
                        packh(acc[mt][nt][0], acc[mt][nt][1]);
                    *(uint32_t*)&kk[(size_t)(r0 + 8) * 1024 + cc] =
                        packh(acc[mt][nt][2], acc[mt][nt][3]);
                } else {
                    uint32_t hi, lo;
                    split2h(acc[mt][nt][0], acc[mt][nt][1], hi, lo);
                    *(uint32_t*)&qh[(size_t)r0 * 1024 + cc] = hi;
                    *(uint32_t*)&ql[(size_t)r0 * 1024 + cc] = lo;
                    split2h(acc[mt][nt][2], acc[mt][nt][3], hi, lo);
                    *(uint32_t*)&qh[(size_t)(r0 + 8) * 1024 + cc] = hi;
                    *(uint32_t*)&ql[(size_t)(r0 + 8) * 1024 + cc] = lo;
                }
            }
        }
    }
}

// ---------------------------------------------------------------------------
// Flash attention, fp16 2-term (S = Qh*K + Ql*K; O += Ph*V + Pl*V).
// j-tile 64, 2 CTAs/SM, register-resident Q and P, term-major ordering.
// SMEM: QH 0, QL 16384; stages s=0,1 at 32768+s*16384: KH+0 (8KB), VH+8192;
//       MASK 65536 + s*256. Total 66048.
// ---------------------------------------------------------------------------
#define AT_QH   0
#define AT_QL   16384
#define AT_STG  32768
#define AT_KH   0
#define AT_VH   8192
#define AT_MASK 65536
#define AT_SMEM 66048

__device__ __forceinline__ void attn_load_stage(
    uint32_t sb, int stage, int j0, int tid, int b, int bh,
    const __half* __restrict__ kk, const __half* __restrict__ vt,
    const float* __restrict__ mask)
{
    uint32_t st = sb + AT_STG + stage * 16384;
    const int h = bh & 15;
    const __half* kg = kk + (size_t)(b * SEQ + j0) * 1024 + h * 64;
#pragma unroll
    for (int i = 0; i < 2; i++) {
        int t = tid + i * 256;          // 0..511
        int row = t >> 3, c = t & 7;
        uint32_t off = SWZ128((uint32_t)(row * 128 + c * 16));
        CP16(st + AT_KH + off, kg + (size_t)row * 1024 + c * 8);
    }
    const __half* vg = vt + (size_t)(bh * 64) * SEQ + j0;
#pragma unroll
    for (int i = 0; i < 2; i++) {
        int t = tid + i * 256;          // 0..511
        int d = t >> 3, c = t & 7;
        uint32_t off = SWZ128((uint32_t)(d * 128 + c * 16));
        CP16(st + AT_VH + off, vg + (size_t)d * SEQ + c * 8);
    }
    if (tid < 16)
        CP16(sb + AT_MASK + stage * 256 + tid * 16, mask + b * SEQ + j0 + tid * 4);
}

__global__ __launch_bounds__(256, 2)
void attn_mma_kernel(const __half* __restrict__ qh,
                     const __half* __restrict__ ql,
                     const __half* __restrict__ kk,
                     const __half* __restrict__ vt,
                     const float* __restrict__ mask,
                     __half* __restrict__ oh,
                     __half* __restrict__ ol)
{
    extern __shared__ char smem[];
    uint32_t sb = smem_u32(smem);
    const int tid = threadIdx.x, lane = tid & 31, w = tid >> 5;
    const int g = lane >> 2, t4 = lane & 3;
    const int l16 = lane & 15, khalf = (lane >> 4) * 16;
    const int bh = blockIdx.y, b = bh >> 4, h = bh & 15;
    const int i0 = blockIdx.x * 128;

    // async-load Q tile (hi+lo) as its own commit group
    {
        const __half* qhg = qh + (size_t)(b * SEQ + i0) * 1024 + h * 64;
        const __half* qlg = ql + (size_t)(b * SEQ + i0) * 1024 + h * 64;
#pragma unroll
        for (int i = 0; i < 4; i++) {
            int t = tid + i * 256;
            int row = t >> 3, c = t & 7;
            uint32_t off = SWZ128((uint32_t)(row * 128 + c * 16));
            CP16(sb + AT_QH + off, qhg + (size_t)row * 1024 + c * 8);
            CP16(sb + AT_QL + off, qlg + (size_t)row * 1024 + c * 8);
        }
    }
    CP_COMMIT();
    attn_load_stage(sb, 0, 0, tid, b, bh, kk, vt, mask);
    CP_COMMIT();

    // Q fragments -> registers
    CP_WAIT1();
    __syncthreads();
    uint32_t qfh[4][4], qfl[4][4];
    const uint32_t qrow = (uint32_t)((w * 16 + l16) * 128);
#pragma unroll
    for (int ks = 0; ks < 4; ks++) {
        uint32_t kb = (uint32_t)(ks * 32 + khalf);
        LDSM4(qfh[ks][0], qfh[ks][1], qfh[ks][2], qfh[ks][3],
              sb + AT_QH + SWZ128(qrow + kb));
        LDSM4(qfl[ks][0], qfl[ks][1], qfl[ks][2], qfl[ks][3],
              sb + AT_QL + SWZ128(qrow + kb));
    }

    float m0 = -1e30f, m1 = -1e30f, lsum0 = 0.0f, lsum1 = 0.0f;
    float o[8][4];
#pragma unroll
    for (int nt = 0; nt < 8; nt++)
#pragma unroll
        for (int v = 0; v < 4; v++) o[nt][v] = 0.0f;

    const float MSC = ATT_SCALE * LOG2E;   // logits in log2 domain

    for (int jt = 0; jt < 32; jt++) {
        CP_WAIT0();
        __syncthreads();
        if (jt + 1 < 32)
            attn_load_stage(sb, (jt + 1) & 1, (jt + 1) * 64, tid, b, bh,
                            kk, vt, mask);
        CP_COMMIT();

        uint32_t stg = sb + AT_STG + (jt & 1) * 16384;
        const float* maskS = (const float*)(smem + AT_MASK + (jt & 1) * 256);

        // ---- S = Q K^T : term-major (Qh*K all, Ql*K all) ----
        float s[8][4];
#pragma unroll
        for (int nt = 0; nt < 8; nt++)
#pragma unroll
            for (int v = 0; v < 4; v++) s[nt][v] = 0.0f;

#pragma unroll
        for (int ks = 0; ks < 4; ks++) {
            const uint32_t kb = (uint32_t)(ks * 32 + khalf);
            uint32_t b4[4][4];
#pragma unroll
            for (int np = 0; np < 4; np++)
                LDSM4(b4[np][0], b4[np][1], b4[np][2], b4[np][3],
                      stg + AT_KH + SWZ128((uint32_t)((np * 16 + l16) * 128) + kb));
#pragma unroll
            for (int np = 0; np < 4; np++) {
                MMA16816(s[np * 2],     qfh[ks], b4[np][0], b4[np][2]);
                MMA16816(s[np * 2 + 1], qfh[ks], b4[np][1], b4[np][3]);
            }
#pragma unroll
            for (int np = 0; np < 4; np++) {
                MMA16816(s[np * 2],     qfl[ks], b4[np][0], b4[np][2]);
                MMA16816(s[np * 2 + 1], qfl[ks], b4[np][1], b4[np][3]);
            }
        }

        // ---- mask*scale*log2e, online softmax (log2 domain) ----
        float rm0 = -1e30f, rm1 = -1e30f;
#pragma unroll
        for (int nt = 0; nt < 8; nt++) {
            float2 mk = *(const float2*)&maskS[nt * 8 + t4 * 2];
            mk.x *= MSC; mk.y *= MSC;
            s[nt][0] *= mk.x; s[nt][1] *= mk.y;
            s[nt][2] *= mk.x; s[nt][3] *= mk.y;
            rm0 = fmaxf(rm0, fmaxf(s[nt][0], s[nt][1]));
            rm1 = fmaxf(rm1, fmaxf(s[nt][2], s[nt][3]));
        }
        rm0 = fmaxf(rm0, __shfl_xor_sync(0xffffffffu, rm0, 1));
        rm0 = fmaxf(rm0, __shfl_xor_sync(0xffffffffu, rm0, 2));
        rm1 = fmaxf(rm1, __shfl_xor_sync(0xffffffffu, rm1, 1));
        rm1 = fmaxf(rm1, __shfl_xor_sync(0xffffffffu, rm1, 2));
        float mn0 = fmaxf(m0, rm0), mn1 = fmaxf(m1, rm1);
        float al0 = exp2f(m0 - mn0), al1 = exp2f(m1 - mn1);
        m0 = mn0; m1 = mn1;
        lsum0 *= al0; lsum1 *= al1;
#pragma unroll
        for (int nt = 0; nt < 8; nt++) {
            o[nt][0] *= al0; o[nt][1] *= al0;
            o[nt][2] *= al1; o[nt][3] *= al1;
        }
        float ps0 = 0.0f, ps1 = 0.0f;
#pragma unroll
        for (int nt = 0; nt < 8; nt++) {
            s[nt][0] = exp2f(s[nt][0] - m0);
            s[nt][1] = exp2f(s[nt][1] - m0);
            s[nt][2] = exp2f(s[nt][2] - m1);
            s[nt][3] = exp2f(s[nt][3] - m1);
            ps0 += s[nt][0] + s[nt][1];
            ps1 += s[nt][2] + s[nt][3];
        }
        lsum0 += ps0; lsum1 += ps1;

        // ---- pack P fragments (S accum frag == A operand frag layout) ----
        uint32_t ph[4][4], pl[4][4];
#pragma unroll
        for (int ks = 0; ks < 4; ks++) {
            split2h(s[2 * ks][0],     s[2 * ks][1],     ph[ks][0], pl[ks][0]);
            split2h(s[2 * ks][2],     s[2 * ks][3],     ph[ks][1], pl[ks][1]);
            split2h(s[2 * ks + 1][0], s[2 * ks + 1][1], ph[ks][2], pl[ks][2]);
            split2h(s[2 * ks + 1][2], s[2 * ks + 1][3], ph[ks][3], pl[ks][3]);
        }

        // ---- O += P V : term-major (Ph*V all, Pl*V all) ----
#pragma unroll
        for (int ks = 0; ks < 4; ks++) {
            const uint32_t kb = (uint32_t)(ks * 32 + khalf);
            uint32_t b4[4][4];
#pragma unroll
            for (int np = 0; np < 4; np++)
                LDSM4(b4[np][0], b4[np][1], b4[np][2], b4[np][3],
                      stg + AT_VH + SWZ128((uint32_t)((np * 16 + l16) * 128) + kb));
#pragma unroll
            for (int np = 0; np < 4; np++) {
                MMA16816(o[np * 2],     ph[ks], b4[np][0], b4[np][2]);
                MMA16816(o[np * 2 + 1], ph[ks], b4[np][1], b4[np][3]);
            }
#pragma unroll
            for (int np = 0; np < 4; np++) {
                MMA16816(o[np * 2],     pl[ks], b4[np][0], b4[np][2]);
                MMA16816(o[np * 2 + 1], pl[ks], b4[np][1], b4[np][3]);
            }
        }
    }

    // ---- finalize: reduce l over quad, normalize, write hi/lo planes ----
    lsum0 += __shfl_xor_sync(0xffffffffu, lsum0, 1);
    lsum0 += __shfl_xor_sync(0xffffffffu, lsum0, 2);
    lsum1 += __shfl_xor_sync(0xffffffffu, lsum1, 1);
    lsum1 += __shfl_xor_sync(0xffffffffu, lsum1, 2);
    float inv0 = 1.0f / lsum0, inv1 = 1.0f / lsum1;

    const int r0 = i0 + w * 16 + g, r1 = r0 + 8;
#pragma unroll
    for (int nt = 0; nt < 8; nt++) {
        int col = nt * 8 + t4 * 2;
        uint32_t hi, lo;
        size_t base0 = (size_t)(b * SEQ + r0) * 1024 + h * 64 + col;
        split2h(o[nt][0] * inv0, o[nt][1] * inv0, hi, lo);
        *(uint32_t*)&oh[base0] = hi;
        *(uint32_t*)&ol[base0] = lo;
        size_t base1 = (size_t)(b * SEQ + r1) * 1024 + h * 64 + col;
        split2h(o[nt][2] * inv1, o[nt][3] * inv1, hi, lo);
        *(uint32_t*)&oh[base1] = hi;
        *(uint32_t*)&ol[base1] = lo;
    }
}

// ---------------------------------------------------------------------------
// Launch
// ---------------------------------------------------------------------------
extern "C" void kernel_launch(void* const* d_in, const int* in_sizes, int n_in,
                              void* d_out, int out_size)
{
    const float* x     = (const float*)d_in[0];
    const float* smask = (const float*)d_in[1];
    const float* wqkv  = (const float*)d_in[2];
    const float* wout  = (const float*)d_in[3];
    float* out = (float*)d_out;

    __half *xh, *xl, *wq, *wo, *ohp, *olp, *qhp, *qlp, *kp, *vtp;
    float* vstp;
    cudaGetSymbolAddress((void**)&xh,  g_xh);
    cudaGetSymbolAddress((void**)&xl,  g_xl);
    cudaGetSymbolAddress((void**)&wq,  g_wq);
    cudaGetSymbolAddress((void**)&wo,  g_wo);
    cudaGetSymbolAddress((void**)&ohp, g_oh);
    cudaGetSymbolAddress((void**)&olp, g_ol);
    cudaGetSymbolAddress((void**)&qhp, g_qh);
    cudaGetSymbolAddress((void**)&qlp, g_ql);
    cudaGetSymbolAddress((void**)&kp,  g_k);
    cudaGetSymbolAddress((void**)&vtp, g_vt);
    cudaGetSymbolAddress((void**)&vstp, g_vst);

    cudaFuncSetAttribute(mma_gemm_kernel, cudaFuncAttributeMaxDynamicSharedMemorySize,
                         GSMEM_BYTES);
    cudaFuncSetAttribute(attn_mma_kernel, cudaFuncAttributeMaxDynamicSharedMemorySize,
                         AT_SMEM);

    // 0) split inputs (x: hi+lo, weights: single fp16)
    split_a_kernel<<<MROWS * 1024 / 256, 256>>>(x, xh, xl, MROWS * 1024);
    split_w_kernel<<<dim3(QKV_COLS / 32, 32), dim3(32, 8)>>>(wqkv, wq, QKV_COLS);
    split_w_kernel<<<dim3(DIM / 32, 32), dim3(32, 8)>>>(wout, wo, DIM);

    // 1) qkv GEMM (2-term fp16); epilogue: Q hi/lo, K fp16, V fp32 staging
    mma_gemm_kernel<<<dim3(QKV_COLS / 128, MROWS / 128), 256, GSMEM_BYTES>>>(
        xh, xl, wq, nullptr, QKV_COLS, 1, qhp, qlp, kp, vstp);

    // 1b) V transpose + fp16 convert
    split_vt_kernel<<<dim3(SEQ / 32, 2, 32), dim3(32, 8)>>>(vstp, vtp);

    // 2) flash attention; epilogue writes hi/lo planes for out-proj
    attn_mma_kernel<<<dim3(SEQ / 128, BATCH * HEADS), 256, AT_SMEM>>>(
        qhp, qlp, kp, vtp, smask, ohp, olp);

    // 3) out projection (2-term fp16)
    mma_gemm_kernel<<<dim3(DIM / 128, MROWS / 128), 256, GSMEM_BYTES>>>(
        ohp, olp, wo, out, DIM, 0, nullptr, nullptr, nullptr, nullptr);
}